// round 4
// baseline (speedup 1.0000x reference)
#include <cuda_runtime.h>
#include <cstdint>
#include <math.h>

#define BATCH 8
#define SEQ   4096
#define EMB   1024
#define HSZ   64

// Scratch for projected Q, K, V (8 MB each). __device__ globals: allocation-free.
__device__ float g_K[BATCH * SEQ * HSZ];
__device__ float g_Q[BATCH * SEQ * HSZ];
__device__ float g_V[BATCH * SEQ * HSZ];

__device__ __forceinline__ uint32_t f2tf32(float f) {
    uint32_t u;
    asm("cvt.rna.tf32.f32 %0, %1;" : "=r"(u) : "f"(f));
    return u;
}

__device__ __forceinline__ void mma_tf32(float c[4], const uint32_t a[4], const uint32_t b[2]) {
    asm volatile(
        "mma.sync.aligned.m16n8k8.row.col.f32.tf32.tf32.f32 "
        "{%0,%1,%2,%3}, {%4,%5,%6,%7}, {%8,%9}, {%0,%1,%2,%3};"
        : "+f"(c[0]), "+f"(c[1]), "+f"(c[2]), "+f"(c[3])
        : "r"(a[0]), "r"(a[1]), "r"(a[2]), "r"(a[3]), "r"(b[0]), "r"(b[1]));
}

// ============================================================================
// Kernel 1: fused QKV projection. X[32768,1024] @ {Wk,Wq,Wv}[1024,64].
// Block = 64 rows, 256 threads = 8 warps laid out 4(m) x 2(n); warp tile m16 x n96.
// Tiles stored in smem pre-converted to tf32 (cvt hoisted out of MMA mainloop).
// ============================================================================
#define PKC 32          // K chunk
#define XS_STRIDE 36    // 64x32 x-tile, padded
#define WS_STRIDE 200   // 32x192 w-tile, padded

__global__ __launch_bounds__(256) void qkv_proj_kernel(
    const float* __restrict__ x,
    const float* __restrict__ Wk,
    const float* __restrict__ Wq,
    const float* __restrict__ Wv)
{
    __shared__ uint32_t xs[64 * XS_STRIDE];
    __shared__ uint32_t ws[PKC * WS_STRIDE];

    const int tid  = threadIdx.x;
    const int wid  = tid >> 5;
    const int lane = tid & 31;
    const int grp  = lane >> 2;   // 0..7
    const int tg   = lane & 3;    // 0..3
    const int wm   = wid & 3;     // warp m index 0..3
    const int wn   = wid >> 2;    // warp n index 0..1
    const int m0   = blockIdx.x * 64;

    float acc[12][4];
    #pragma unroll
    for (int i = 0; i < 12; i++)
        #pragma unroll
        for (int j = 0; j < 4; j++) acc[i][j] = 0.f;

    for (int k0 = 0; k0 < EMB; k0 += PKC) {
        __syncthreads();
        // load x tile: 64 rows x 32 cols = 512 float4, cvt to tf32 at store
        #pragma unroll
        for (int i = tid; i < 512; i += 256) {
            int r = i >> 3, c4 = i & 7;
            float4 v = *(const float4*)(x + (size_t)(m0 + r) * EMB + k0 + c4 * 4);
            uint4 u = make_uint4(f2tf32(v.x), f2tf32(v.y), f2tf32(v.z), f2tf32(v.w));
            *(uint4*)&xs[r * XS_STRIDE + c4 * 4] = u;
        }
        // load W tiles: 3 projections x 32x64 = 1536 float4. cols: [K|Q|V]
        #pragma unroll
        for (int i = tid; i < 1536; i += 256) {
            int p  = i >> 9;
            int r  = (i >> 4) & 31;
            int c4 = i & 15;
            const float* wp = (p == 0) ? Wk : ((p == 1) ? Wq : Wv);
            float4 v = *(const float4*)(wp + (size_t)(k0 + r) * HSZ + c4 * 4);
            uint4 u = make_uint4(f2tf32(v.x), f2tf32(v.y), f2tf32(v.z), f2tf32(v.w));
            *(uint4*)&ws[r * WS_STRIDE + p * 64 + c4 * 4] = u;
        }
        __syncthreads();

        #pragma unroll
        for (int kk = 0; kk < PKC; kk += 8) {
            uint32_t a[4];
            const int row = wm * 16 + grp;
            a[0] = xs[row * XS_STRIDE + kk + tg];
            a[1] = xs[(row + 8) * XS_STRIDE + kk + tg];
            a[2] = xs[row * XS_STRIDE + kk + tg + 4];
            a[3] = xs[(row + 8) * XS_STRIDE + kk + tg + 4];
            #pragma unroll
            for (int nt = 0; nt < 12; nt++) {
                const int n = wn * 96 + nt * 8 + grp;
                uint32_t b[2];
                b[0] = ws[(kk + tg) * WS_STRIDE + n];
                b[1] = ws[(kk + tg + 4) * WS_STRIDE + n];
                mma_tf32(acc[nt], a, b);
            }
        }
    }

    // epilogue: scatter into g_K / g_Q / g_V (col 0-63 -> K, 64-127 -> Q, 128-191 -> V)
    #pragma unroll
    for (int nt = 0; nt < 12; nt++) {
        const int colbase = wn * 96 + nt * 8 + 2 * tg;
        const int p = colbase >> 6;             // constant within an 8-wide ntile
        float* dst = (p == 0) ? g_K : ((p == 1) ? g_Q : g_V);
        const int h0 = colbase & 63;
        const int r0 = m0 + wm * 16 + grp;
        dst[(size_t)r0 * HSZ + h0]           = acc[nt][0];
        dst[(size_t)r0 * HSZ + h0 + 1]       = acc[nt][1];
        dst[(size_t)(r0 + 8) * HSZ + h0]     = acc[nt][2];
        dst[(size_t)(r0 + 8) * HSZ + h0 + 1] = acc[nt][3];
    }
}

// ============================================================================
// Kernel 2: causal flash attention, 128-query tiles x 64-key tiles, tf32 mma.
// 256 threads = 8 warps; warp w owns query rows [w*16, w*16+16).
// Ping-pong K/V smem buffers + register prefetch: one __syncthreads per tile.
// K/V/P stored in smem pre-converted to tf32; the softmax l-sum uses the SAME
// tf32-rounded p values as the PV matmul (consistent normalization).
// Grid is flat 1D, globally sorted heaviest-tile-first (LPT) for wave balance.
// Dynamic smem: sK0|sV0|sK1|sV1 (each 64x68) | sP (128x68, doubles as Q stage).
// ============================================================================
#define KV_STRIDE 68
#define P_STRIDE  68
#define KV_TILE   (64 * KV_STRIDE)
#define NTILES    (SEQ / 128)
#define ATTN_SMEM ((4 * KV_TILE + 128 * P_STRIDE) * 4)

__global__ __launch_bounds__(256) void attn_kernel(float* __restrict__ out)
{
    extern __shared__ uint32_t smem[];
    uint32_t* sP = smem + 4 * KV_TILE;

    const int tid  = threadIdx.x;
    const int wid  = tid >> 5;
    const int lane = tid & 31;
    const int grp  = lane >> 2;
    const int tg   = lane & 3;

    // global LPT order: all batches' heaviest tiles launch first
    const int flat = blockIdx.x;
    const int tile = NTILES - 1 - (flat >> 3);   // 31, 31, ..(x8).., 30, ...
    const int b    = flat & 7;
    const int m0   = tile * 128;

    const float* qb = g_Q + (size_t)b * SEQ * HSZ;
    const float* kb = g_K + (size_t)b * SEQ * HSZ;
    const float* vb = g_V + (size_t)b * SEQ * HSZ;

    // stage Q tile (scaled, tf32) into sP; scale = C^-0.5 = 1/32
    #pragma unroll
    for (int i = tid; i < 128 * 16; i += 256) {
        int r = i >> 4, c4 = i & 15;
        float4 v = *(const float4*)(qb + (size_t)(m0 + r) * HSZ + c4 * 4);
        uint4 u = make_uint4(f2tf32(v.x * 0.03125f), f2tf32(v.y * 0.03125f),
                             f2tf32(v.z * 0.03125f), f2tf32(v.w * 0.03125f));
        *(uint4*)&sP[r * P_STRIDE + c4 * 4] = u;
    }
    __syncthreads();

    uint32_t qf[8][4];
    {
        const int row = wid * 16 + grp;
        #pragma unroll
        for (int kk = 0; kk < 8; kk++) {
            qf[kk][0] = sP[row * P_STRIDE + kk * 8 + tg];
            qf[kk][1] = sP[(row + 8) * P_STRIDE + kk * 8 + tg];
            qf[kk][2] = sP[row * P_STRIDE + kk * 8 + tg + 4];
            qf[kk][3] = sP[(row + 8) * P_STRIDE + kk * 8 + tg + 4];
        }
    }

    float o[8][4];
    #pragma unroll
    for (int i = 0; i < 8; i++)
        #pragma unroll
        for (int j = 0; j < 4; j++) o[i][j] = 0.f;
    float m_row[2] = {-INFINITY, -INFINITY};
    float l_row[2] = {0.f, 0.f};

    const int jmax = 2 * tile + 1;          // key tiles 0 .. jmax
    const int prow = wid * 16 + grp;

    // prefetch K/V tile 0 into registers (4 float4 each per thread)
    const int pr = tid >> 4;        // base row (this thread covers pr, pr+16, +32, +48)
    const int pc = (tid & 15) * 4;  // col
    float4 pk[4], pv[4];
    #pragma unroll
    for (int i = 0; i < 4; i++) {
        pk[i] = *(const float4*)(kb + (size_t)(pr + i * 16) * HSZ + pc);
        pv[i] = *(const float4*)(vb + (size_t)(pr + i * 16) * HSZ + pc);
    }

    for (int j = 0; j <= jmax; j++) {
        uint32_t* sK = smem + (j & 1) * 2 * KV_TILE;
        uint32_t* sV = sK + KV_TILE;
        const int s0 = j * 64;

        // commit prefetched tile j to smem (cvt to tf32 at store).
        // Race-free: passing the barrier below at iter j-1 guaranteed all warps
        // finished compute of iter j-2, the last reader of this buffer.
        #pragma unroll
        for (int i = 0; i < 4; i++) {
            const int r = pr + i * 16;
            *(uint4*)&sK[r * KV_STRIDE + pc] =
                make_uint4(f2tf32(pk[i].x), f2tf32(pk[i].y), f2tf32(pk[i].z), f2tf32(pk[i].w));
            *(uint4*)&sV[r * KV_STRIDE + pc] =
                make_uint4(f2tf32(pv[i].x), f2tf32(pv[i].y), f2tf32(pv[i].z), f2tf32(pv[i].w));
        }
        __syncthreads();

        // issue global loads for tile j+1; latency hidden behind compute below
        if (j < jmax) {
            const size_t nb = (size_t)(s0 + 64) * HSZ;
            #pragma unroll
            for (int i = 0; i < 4; i++) {
                pk[i] = *(const float4*)(kb + nb + (size_t)(pr + i * 16) * HSZ + pc);
                pv[i] = *(const float4*)(vb + nb + (size_t)(pr + i * 16) * HSZ + pc);
            }
        }

        // S = Qs * K^T  (per-warp m16 x n64)
        float s[8][4];
        #pragma unroll
        for (int nt = 0; nt < 8; nt++) {
            s[nt][0] = s[nt][1] = s[nt][2] = s[nt][3] = 0.f;
            #pragma unroll
            for (int kk = 0; kk < 8; kk++) {
                uint32_t bf[2];
                bf[0] = sK[(nt * 8 + grp) * KV_STRIDE + kk * 8 + tg];
                bf[1] = sK[(nt * 8 + grp) * KV_STRIDE + kk * 8 + tg + 4];
                mma_tf32(s[nt], qf[kk], bf);
            }
        }

        // causal mask (only tiles that cross the diagonal: s0 >= m0)
        if (s0 >= m0) {
            const int mA = m0 + wid * 16 + grp;
            #pragma unroll
            for (int nt = 0; nt < 8; nt++) {
                const int c0 = s0 + nt * 8 + 2 * tg;
                if (c0 > mA)         s[nt][0] = -INFINITY;
                if (c0 + 1 > mA)     s[nt][1] = -INFINITY;
                if (c0 > mA + 8)     s[nt][2] = -INFINITY;
                if (c0 + 1 > mA + 8) s[nt][3] = -INFINITY;
            }
        }

        // online softmax: rows prow and prow+8 per thread, reduced over the quad
        float mx0 = -INFINITY, mx1 = -INFINITY;
        #pragma unroll
        for (int nt = 0; nt < 8; nt++) {
            mx0 = fmaxf(mx0, fmaxf(s[nt][0], s[nt][1]));
            mx1 = fmaxf(mx1, fmaxf(s[nt][2], s[nt][3]));
        }
        mx0 = fmaxf(mx0, __shfl_xor_sync(0xffffffffu, mx0, 1));
        mx0 = fmaxf(mx0, __shfl_xor_sync(0xffffffffu, mx0, 2));
        mx1 = fmaxf(mx1, __shfl_xor_sync(0xffffffffu, mx1, 1));
        mx1 = fmaxf(mx1, __shfl_xor_sync(0xffffffffu, mx1, 2));

        const float mn0 = fmaxf(m_row[0], mx0);
        const float mn1 = fmaxf(m_row[1], mx1);
        const float al0 = __expf(m_row[0] - mn0);
        const float al1 = __expf(m_row[1] - mn1);

        float sum0 = 0.f, sum1 = 0.f;
        #pragma unroll
        for (int nt = 0; nt < 8; nt++) {
            const int col = nt * 8 + 2 * tg;
            uint32_t u0 = f2tf32(__expf(s[nt][0] - mn0));
            uint32_t u1 = f2tf32(__expf(s[nt][1] - mn0));
            uint32_t u2 = f2tf32(__expf(s[nt][2] - mn1));
            uint32_t u3 = f2tf32(__expf(s[nt][3] - mn1));
            // consistent normalization: sum the tf32-rounded probabilities
            sum0 += __uint_as_float(u0) + __uint_as_float(u1);
            sum1 += __uint_as_float(u2) + __uint_as_float(u3);
            sP[prow * P_STRIDE + col]           = u0;
            sP[prow * P_STRIDE + col + 1]       = u1;
            sP[(prow + 8) * P_STRIDE + col]     = u2;
            sP[(prow + 8) * P_STRIDE + col + 1] = u3;
        }
        sum0 += __shfl_xor_sync(0xffffffffu, sum0, 1);
        sum0 += __shfl_xor_sync(0xffffffffu, sum0, 2);
        sum1 += __shfl_xor_sync(0xffffffffu, sum1, 1);
        sum1 += __shfl_xor_sync(0xffffffffu, sum1, 2);

        l_row[0] = l_row[0] * al0 + sum0;
        l_row[1] = l_row[1] * al1 + sum1;
        m_row[0] = mn0;
        m_row[1] = mn1;

        #pragma unroll
        for (int nt = 0; nt < 8; nt++) {
            o[nt][0] *= al0; o[nt][1] *= al0;
            o[nt][2] *= al1; o[nt][3] *= al1;
        }
        __syncwarp();   // warp-private sP band now visible to all its lanes

        // O += P * V
        #pragma unroll
        for (int kk = 0; kk < 8; kk++) {
            uint32_t a[4];
            a[0] = sP[prow * P_STRIDE + kk * 8 + tg];
            a[1] = sP[(prow + 8) * P_STRIDE + kk * 8 + tg];
            a[2] = sP[prow * P_STRIDE + kk * 8 + tg + 4];
            a[3] = sP[(prow + 8) * P_STRIDE + kk * 8 + tg + 4];
            #pragma unroll
            for (int nt = 0; nt < 8; nt++) {
                uint32_t bf[2];
                bf[0] = sV[(kk * 8 + tg) * KV_STRIDE + nt * 8 + grp];
                bf[1] = sV[(kk * 8 + tg + 4) * KV_STRIDE + nt * 8 + grp];
                mma_tf32(o[nt], a, bf);
            }
        }
    }

    // epilogue: normalize and write [B, T, HS]
    const float inv0 = 1.f / l_row[0];
    const float inv1 = 1.f / l_row[1];
    const int r0 = m0 + wid * 16 + grp;
    float* ob = out + (size_t)b * SEQ * HSZ;
    #pragma unroll
    for (int nt = 0; nt < 8; nt++) {
        const int h = nt * 8 + 2 * tg;
        ob[(size_t)r0 * HSZ + h]           = o[nt][0] * inv0;
        ob[(size_t)r0 * HSZ + h + 1]       = o[nt][1] * inv0;
        ob[(size_t)(r0 + 8) * HSZ + h]     = o[nt][2] * inv1;
        ob[(size_t)(r0 + 8) * HSZ + h + 1] = o[nt][3] * inv1;
    }
}

// ============================================================================
extern "C" void kernel_launch(void* const* d_in, const int* in_sizes, int n_in,
                              void* d_out, int out_size)
{
    const float* x  = (const float*)d_in[0];
    const float* Wk = (const float*)d_in[1];
    const float* Wq = (const float*)d_in[2];
    const float* Wv = (const float*)d_in[3];
    float* out = (float*)d_out;

    cudaFuncSetAttribute(attn_kernel, cudaFuncAttributeMaxDynamicSharedMemorySize, ATTN_SMEM);

    qkv_proj_kernel<<<(BATCH * SEQ) / 64, 256>>>(x, Wk, Wq, Wv);
    attn_kernel<<<NTILES * BATCH, 256, ATTN_SMEM>>>(out);
}

// round 13
// speedup vs baseline: 1.9590x; 1.9590x over previous
#include <cuda_runtime.h>
#include <cuda_fp16.h>
#include <cstdint>
#include <math.h>

#define BATCH 8
#define SEQ   4096
#define EMB   1024
#define HSZ   64

// fp16 scratch. g_Q is pre-scaled by C^-0.5 = 1/32. g_VT is [batch][dim][seq].
__device__ __half g_K [BATCH * SEQ * HSZ];
__device__ __half g_Q [BATCH * SEQ * HSZ];
__device__ __half g_VT[BATCH * HSZ * SEQ];
__device__ __half g_Wt[3 * HSZ * EMB];       // [p*64+h][c], transposed, Q pre-scaled

__device__ __forceinline__ void mma_f16(float c[4], const uint32_t a[4], const uint32_t b[2]) {
    asm volatile(
        "mma.sync.aligned.m16n8k16.row.col.f32.f16.f16.f32 "
        "{%0,%1,%2,%3}, {%4,%5,%6,%7}, {%8,%9}, {%0,%1,%2,%3};"
        : "+f"(c[0]), "+f"(c[1]), "+f"(c[2]), "+f"(c[3])
        : "r"(a[0]), "r"(a[1]), "r"(a[2]), "r"(a[3]), "r"(b[0]), "r"(b[1]));
}

__device__ __forceinline__ uint32_t pack2(float a, float b) {
    __half2 h = __floats2half2_rn(a, b);
    return *(uint32_t*)&h;
}

// ============================================================================
// Kernel 0: transpose W [1024][64] f32 -> g_Wt [192][1024] fp16 (Q scaled 1/32)
// ============================================================================
__global__ __launch_bounds__(256) void prep_w_kernel(
    const float* __restrict__ Wk, const float* __restrict__ Wq, const float* __restrict__ Wv)
{
    __shared__ float t[64][65];
    const int p  = blockIdx.y;
    const int c0 = blockIdx.x * 64;
    const float* W = (p == 0) ? Wk : ((p == 1) ? Wq : Wv);
    const float scale = (p == 1) ? 0.03125f : 1.0f;

    #pragma unroll
    for (int j = 0; j < 16; j++) {
        int idx = threadIdx.x + j * 256;
        int c = idx >> 6, h = idx & 63;
        t[c][h] = W[(size_t)(c0 + c) * HSZ + h];
    }
    __syncthreads();
    #pragma unroll
    for (int j = 0; j < 16; j++) {
        int idx = threadIdx.x + j * 256;
        int h = idx >> 6, c = idx & 63;
        g_Wt[(size_t)(p * 64 + h) * EMB + c0 + c] = __float2half_rn(t[c][h] * scale);
    }
}

// ============================================================================
// Kernel 1: fused QKV projection, fp16 mma m16n8k16, K-chunk = 64, with
// register prefetch of the next chunk (LDG latency hidden behind the MMA
// phase of the current chunk; same pattern as the attention pipeline).
// Block = 64 rows, 256 thr = 8 warps (4m x 2n); warp tile m16 x n96.
// ============================================================================
#define PKC 64
#define XSW 36      // x-tile word stride  (72 halfs: 64 data + pad)
#define WTW 36      // wt-tile word stride

__global__ __launch_bounds__(256) void qkv_proj_kernel(const float* __restrict__ x)
{
    __shared__ uint32_t xs[64 * XSW];     // 9 KB
    __shared__ uint32_t wt[192 * WTW];    // 27 KB

    const int tid  = threadIdx.x;
    const int wid  = tid >> 5;
    const int lane = tid & 31;
    const int grp  = lane >> 2;
    const int tg   = lane & 3;
    const int wm   = wid & 3;
    const int wn   = wid >> 2;
    const int m0   = blockIdx.x * 64;

    // per-thread staging coordinates
    const int xr = tid >> 2, xc = (tid & 3) * 16;     // x: row, col-base (16 cols)
    const float* xrow = x + (size_t)(m0 + xr) * EMB + xc;

    float acc[12][4];
    #pragma unroll
    for (int i = 0; i < 12; i++)
        #pragma unroll
        for (int j = 0; j < 4; j++) acc[i][j] = 0.f;

    // prefetch chunk 0
    float4 px[4];
    uint4  pw[6];
    #pragma unroll
    for (int q = 0; q < 4; q++) px[q] = *(const float4*)(xrow + q * 4);
    #pragma unroll
    for (int i = 0; i < 3; i++) {
        const int u = tid + i * 256;
        const int r = u >> 2, ch = (u & 3) * 16;
        const __half* wp = g_Wt + (size_t)r * EMB + ch;
        pw[i * 2]     = *(const uint4*)wp;
        pw[i * 2 + 1] = *(const uint4*)(wp + 8);
    }

    for (int k0 = 0; k0 < EMB; k0 += PKC) {
        __syncthreads();   // previous chunk's MMA readers done
        // commit prefetched chunk to smem
        {
            uint4 ua, ub;
            ua.x = pack2(px[0].x, px[0].y); ua.y = pack2(px[0].z, px[0].w);
            ua.z = pack2(px[1].x, px[1].y); ua.w = pack2(px[1].z, px[1].w);
            ub.x = pack2(px[2].x, px[2].y); ub.y = pack2(px[2].z, px[2].w);
            ub.z = pack2(px[3].x, px[3].y); ub.w = pack2(px[3].z, px[3].w);
            *(uint4*)&xs[xr * XSW + (tid & 3) * 8]     = ua;
            *(uint4*)&xs[xr * XSW + (tid & 3) * 8 + 4] = ub;
        }
        #pragma unroll
        for (int i = 0; i < 3; i++) {
            const int u = tid + i * 256;
            const int r = u >> 2;
            *(uint4*)&wt[r * WTW + (u & 3) * 8]     = pw[i * 2];
            *(uint4*)&wt[r * WTW + (u & 3) * 8 + 4] = pw[i * 2 + 1];
        }
        __syncthreads();

        // issue prefetch for chunk k0+64; latency hidden behind MMA below
        if (k0 + PKC < EMB) {
            const int kn = k0 + PKC;
            #pragma unroll
            for (int q = 0; q < 4; q++) px[q] = *(const float4*)(xrow + kn + q * 4);
            #pragma unroll
            for (int i = 0; i < 3; i++) {
                const int u = tid + i * 256;
                const int r = u >> 2, ch = (u & 3) * 16;
                const __half* wp = g_Wt + (size_t)r * EMB + kn + ch;
                pw[i * 2]     = *(const uint4*)wp;
                pw[i * 2 + 1] = *(const uint4*)(wp + 8);
            }
        }

        #pragma unroll
        for (int kk = 0; kk < 4; kk++) {
            uint32_t a[4];
            const int row = wm * 16 + grp;
            a[0] = xs[row * XSW + kk * 8 + tg];
            a[1] = xs[(row + 8) * XSW + kk * 8 + tg];
            a[2] = xs[row * XSW + kk * 8 + tg + 4];
            a[3] = xs[(row + 8) * XSW + kk * 8 + tg + 4];
            #pragma unroll
            for (int nt = 0; nt < 12; nt++) {
                const int n = wn * 96 + nt * 8 + grp;
                uint32_t b[2];
                b[0] = wt[n * WTW + kk * 8 + tg];
                b[1] = wt[n * WTW + kk * 8 + tg + 4];
                mma_f16(acc[nt], a, b);
            }
        }
    }

    // epilogue: K,Q -> row-major fp16; V -> g_VT [batch][dim][seq] fp16
    #pragma unroll
    for (int nt = 0; nt < 12; nt++) {
        const int colbase = wn * 96 + nt * 8 + 2 * tg;
        const int p  = colbase >> 6;
        const int h0 = colbase & 63;
        const int r0 = m0 + wm * 16 + grp;
        if (p < 2) {
            __half* dst = (p == 0) ? g_K : g_Q;
            *(uint32_t*)(dst + (size_t)r0 * HSZ + h0)       = pack2(acc[nt][0], acc[nt][1]);
            *(uint32_t*)(dst + (size_t)(r0 + 8) * HSZ + h0) = pack2(acc[nt][2], acc[nt][3]);
        } else {
            const int b1 = r0 >> 12, s1 = r0 & 4095;
            __half* vt = g_VT + (size_t)b1 * HSZ * SEQ;
            vt[(size_t)h0 * SEQ + s1]             = __float2half_rn(acc[nt][0]);
            vt[(size_t)(h0 + 1) * SEQ + s1]       = __float2half_rn(acc[nt][1]);
            vt[(size_t)h0 * SEQ + s1 + 8]         = __float2half_rn(acc[nt][2]);
            vt[(size_t)(h0 + 1) * SEQ + s1 + 8]   = __float2half_rn(acc[nt][3]);
        }
    }
}

// ============================================================================
// Kernel 2: causal flash attention, fp16 mma m16n8k16, 128q x 64k tiles.
// 256 thr = 8 warps; ping-pong K/VT smem + uint4 register prefetch.
// sVT is dim-major so PV B-fragments are half2-contiguous (no transpose).
// __launch_bounds__(256,2): 2 CTAs/SM, single wave (256 CTAs <= 296 slots).
// ============================================================================
#define KVW      36                 // 72 halfs word stride
#define KV_TILE  (64 * KVW)
#define PW       36                 // sP word stride (72 halfs)
#define NTILES   (SEQ / 128)
#define ATTN_SMEM ((4 * KV_TILE + 128 * PW) * 4)

__global__ __launch_bounds__(256, 2) void attn_kernel(float* __restrict__ out)
{
    extern __shared__ uint32_t smem[];
    uint32_t* sP = smem + 4 * KV_TILE;

    const int tid  = threadIdx.x;
    const int wid  = tid >> 5;
    const int lane = tid & 31;
    const int grp  = lane >> 2;
    const int tg   = lane & 3;

    const int flat = blockIdx.x;
    const int tile = NTILES - 1 - (flat >> 3);   // heaviest first (global LPT)
    const int b    = flat & 7;
    const int m0   = tile * 128;

    const __half* qb  = g_Q  + (size_t)b * SEQ * HSZ;
    const __half* kb  = g_K  + (size_t)b * SEQ * HSZ;
    const __half* vtb = g_VT + (size_t)b * HSZ * SEQ;

    // stage Q tile (fp16, pre-scaled) into sP: 128x64 halfs = 1024 uint4
    #pragma unroll
    for (int i = 0; i < 4; i++) {
        const int u = tid + i * 256;
        const int r = u >> 3, c = u & 7;
        *(uint4*)&sP[r * PW + c * 4] =
            *(const uint4*)(qb + (size_t)(m0 + r) * HSZ + c * 8);
    }
    __syncthreads();

    uint32_t qf[4][4];
    {
        const int row = wid * 16 + grp;
        #pragma unroll
        for (int kk = 0; kk < 4; kk++) {
            qf[kk][0] = sP[row * PW + kk * 8 + tg];
            qf[kk][1] = sP[(row + 8) * PW + kk * 8 + tg];
            qf[kk][2] = sP[row * PW + kk * 8 + tg + 4];
            qf[kk][3] = sP[(row + 8) * PW + kk * 8 + tg + 4];
        }
    }

    float o[8][4];
    #pragma unroll
    for (int i = 0; i < 8; i++)
        #pragma unroll
        for (int j = 0; j < 4; j++) o[i][j] = 0.f;
    float m_row[2] = {-INFINITY, -INFINITY};
    float l_row[2] = {0.f, 0.f};

    const int jmax = 2 * tile + 1;
    const int prow = wid * 16 + grp;

    // prefetch tile 0: K rows / VT rows, 512 uint4 each tile -> 2 per thread
    const int kr0 = tid >> 3,         kc0 = tid & 7;
    const int kr1 = (tid + 256) >> 3, kc1 = tid & 7;
    uint4 pk0, pk1, pv0, pv1;
    pk0 = *(const uint4*)(kb  + (size_t)kr0 * HSZ + kc0 * 8);
    pk1 = *(const uint4*)(kb  + (size_t)kr1 * HSZ + kc1 * 8);
    pv0 = *(const uint4*)(vtb + (size_t)kr0 * SEQ + kc0 * 8);
    pv1 = *(const uint4*)(vtb + (size_t)kr1 * SEQ + kc1 * 8);

    for (int j = 0; j <= jmax; j++) {
        uint32_t* sK  = smem + (j & 1) * 2 * KV_TILE;
        uint32_t* sVT = sK + KV_TILE;
        const int s0 = j * 64;

        // commit prefetched tile j (race-free: barrier j-1 guaranteed all warps
        // finished compute j-2, the last reader of this buffer)
        *(uint4*)&sK [kr0 * KVW + kc0 * 4] = pk0;
        *(uint4*)&sK [kr1 * KVW + kc1 * 4] = pk1;
        *(uint4*)&sVT[kr0 * KVW + kc0 * 4] = pv0;
        *(uint4*)&sVT[kr1 * KVW + kc1 * 4] = pv1;
        __syncthreads();

        // prefetch tile j+1; latency hidden behind compute below
        if (j < jmax) {
            const int sn = s0 + 64;
            pk0 = *(const uint4*)(kb  + (size_t)(sn + kr0) * HSZ + kc0 * 8);
            pk1 = *(const uint4*)(kb  + (size_t)(sn + kr1) * HSZ + kc1 * 8);
            pv0 = *(const uint4*)(vtb + (size_t)kr0 * SEQ + sn + kc0 * 8);
            pv1 = *(const uint4*)(vtb + (size_t)kr1 * SEQ + sn + kc1 * 8);
        }

        // S = Qs * K^T : per-warp m16 x n64, K=64 in 4 k-steps
        float s[8][4];
        #pragma unroll
        for (int nt = 0; nt < 8; nt++) {
            s[nt][0] = s[nt][1] = s[nt][2] = s[nt][3] = 0.f;
            #pragma unroll
            for (int kk = 0; kk < 4; kk++) {
                uint32_t bf[2];
                bf[0] = sK[(nt * 8 + grp) * KVW + kk * 8 + tg];
                bf[1] = sK[(nt * 8 + grp) * KVW + kk * 8 + tg + 4];
                mma_f16(s[nt], qf[kk], bf);
            }
        }

        // causal mask on diagonal-crossing tiles
        if (s0 >= m0) {
            const int mA = m0 + wid * 16 + grp;
            #pragma unroll
            for (int nt = 0; nt < 8; nt++) {
                const int c0 = s0 + nt * 8 + 2 * tg;
                if (c0 > mA)         s[nt][0] = -INFINITY;
                if (c0 + 1 > mA)     s[nt][1] = -INFINITY;
                if (c0 > mA + 8)     s[nt][2] = -INFINITY;
                if (c0 + 1 > mA + 8) s[nt][3] = -INFINITY;
            }
        }

        // online softmax (quad reduction over tg)
        float mx0 = -INFINITY, mx1 = -INFINITY;
        #pragma unroll
        for (int nt = 0; nt < 8; nt++) {
            mx0 = fmaxf(mx0, fmaxf(s[nt][0], s[nt][1]));
            mx1 = fmaxf(mx1, fmaxf(s[nt][2], s[nt][3]));
        }
        mx0 = fmaxf(mx0, __shfl_xor_sync(0xffffffffu, mx0, 1));
        mx0 = fmaxf(mx0, __shfl_xor_sync(0xffffffffu, mx0, 2));
        mx1 = fmaxf(mx1, __shfl_xor_sync(0xffffffffu, mx1, 1));
        mx1 = fmaxf(mx1, __shfl_xor_sync(0xffffffffu, mx1, 2));

        const float mn0 = fmaxf(m_row[0], mx0);
        const float mn1 = fmaxf(m_row[1], mx1);
        const float al0 = __expf(m_row[0] - mn0);
        const float al1 = __expf(m_row[1] - mn1);

        float sum0 = 0.f, sum1 = 0.f;
        #pragma unroll
        for (int nt = 0; nt < 8; nt++) {
            __half2 h01 = __floats2half2_rn(__expf(s[nt][0] - mn0), __expf(s[nt][1] - mn0));
            __half2 h23 = __floats2half2_rn(__expf(s[nt][2] - mn1), __expf(s[nt][3] - mn1));
            // consistent normalization: sum the fp16-rounded probabilities
            float2 f01 = __half22float2(h01);
            float2 f23 = __half22float2(h23);
            sum0 += f01.x + f01.y;
            sum1 += f23.x + f23.y;
            sP[prow * PW + nt * 4 + tg]       = *(uint32_t*)&h01;
            sP[(prow + 8) * PW + nt * 4 + tg] = *(uint32_t*)&h23;
        }
        sum0 += __shfl_xor_sync(0xffffffffu, sum0, 1);
        sum0 += __shfl_xor_sync(0xffffffffu, sum0, 2);
        sum1 += __shfl_xor_sync(0xffffffffu, sum1, 1);
        sum1 += __shfl_xor_sync(0xffffffffu, sum1, 2);

        l_row[0] = l_row[0] * al0 + sum0;
        l_row[1] = l_row[1] * al1 + sum1;
        m_row[0] = mn0;
        m_row[1] = mn1;

        #pragma unroll
        for (int nt = 0; nt < 8; nt++) {
            o[nt][0] *= al0; o[nt][1] *= al0;
            o[nt][2] *= al1; o[nt][3] *= al1;
        }
        __syncwarp();   // warp-private sP band visible to all lanes

        // O += P * V : A = P [m16 k64] fp16 from sP, B = V^T rows in sVT
        #pragma unroll
        for (int kk = 0; kk < 4; kk++) {
            uint32_t a[4];
            a[0] = sP[prow * PW + kk * 8 + tg];
            a[1] = sP[(prow + 8) * PW + kk * 8 + tg];
            a[2] = sP[prow * PW + kk * 8 + tg + 4];
            a[3] = sP[(prow + 8) * PW + kk * 8 + tg + 4];
            #pragma unroll
            for (int nt = 0; nt < 8; nt++) {
                uint32_t bf[2];
                bf[0] = sVT[(nt * 8 + grp) * KVW + kk * 8 + tg];
                bf[1] = sVT[(nt * 8 + grp) * KVW + kk * 8 + tg + 4];
                mma_f16(o[nt], a, bf);
            }
        }
    }

    // epilogue: normalize, vectorized float2 stores
    const float inv0 = 1.f / l_row[0];
    const float inv1 = 1.f / l_row[1];
    const int r0 = m0 + wid * 16 + grp;
    float* ob = out + (size_t)b * SEQ * HSZ;
    #pragma unroll
    for (int nt = 0; nt < 8; nt++) {
        const int h = nt * 8 + 2 * tg;
        *(float2*)(ob + (size_t)r0 * HSZ + h)       = make_float2(o[nt][0] * inv0, o[nt][1] * inv0);
        *(float2*)(ob + (size_t)(r0 + 8) * HSZ + h) = make_float2(o[nt][2] * inv1, o[nt][3] * inv1);
    }
}

// ============================================================================
extern "C" void kernel_launch(void* const* d_in, const int* in_sizes, int n_in,
                              void* d_out, int out_size)
{
    const float* x  = (const float*)d_in[0];
    const float* Wk = (const float*)d_in[1];
    const float* Wq = (const float*)d_in[2];
    const float* Wv = (const float*)d_in[3];
    float* out = (float*)d_out;

    cudaFuncSetAttribute(attn_kernel, cudaFuncAttributeMaxDynamicSharedMemorySize, ATTN_SMEM);

    prep_w_kernel<<<dim3(EMB / 64, 3), 256>>>(Wk, Wq, Wv);
    qkv_proj_kernel<<<(BATCH * SEQ) / 64, 256>>>(x);
    attn_kernel<<<NTILES * BATCH, 256, ATTN_SMEM>>>(out);
}